// round 4
// baseline (speedup 1.0000x reference)
#include <cuda_runtime.h>
#include <cuda_bf16.h>

// Gemma4VisionPooler: 2x2 segment-mean pool (B=16, L=4096 -> 1024, H=1152) * sqrt(H)
// R3: packed int4 gather lists (sentinel -1), padding filtered at index build,
// streaming cache hints, widened index-build kernels.

#define BATCH  16
#define LIN    4096
#define HID    1152
#define OUTLEN 1024
#define KPOOL  2          // sqrt(LIN/OUTLEN)
#define SLOTS  4          // k^2 rows per segment
#define H4     (HID / 4)  // 288 float4 per row
#define NSEG   (BATCH * OUTLEN)

// Scratch (allocation-free rule: __device__ globals)
__device__ int  g_cnt[NSEG];    // total rows per segment (incl. padded) -> mask
__device__ int  g_vcnt[NSEG];   // valid (non-padded) slot cursor
__device__ int4 g_idx4[NSEG];   // packed absolute row ids, -1 = empty
__device__ int  g_maxx[BATCH];  // per-batch max clamped x
__device__ int  g_is32;         // 1 if positions are int32

// ---------------------------------------------------------------------------
// Kernel A: reset scratch + dtype detect + per-batch max_x.
// grid = 64 blocks x 256 threads.
// ---------------------------------------------------------------------------
__global__ void prep_kernel(const int* __restrict__ p32) {
    const int gtid = blockIdx.x * blockDim.x + threadIdx.x;
    const int nthr = gridDim.x * blockDim.x;

    // reset
    for (int i = gtid; i < NSEG; i += nthr) {
        g_cnt[i]  = 0;
        g_vcnt[i] = 0;
        g_idx4[i] = make_int4(-1, -1, -1, -1);
    }
    if (gtid < BATCH) g_maxx[gtid] = 0;
    if (gtid == 0)    g_is32 = 0;
    // make resets visible before kernel B reads them (separate launch = ordered)

    // dtype detect + per-batch max over clamped x, viewing buffer as int32 words.
    // int64 layout: words {xlo,xhi,ylo,yhi}; odd words (hi) are 0/-1.
    // int32 layout: words {x,y}; odd words are y, which exceed 0 somewhere.
    int is32_local = 0;
    int lmax[1];  // per-thread running max for its batches: track per-iteration batch
    (void)lmax;
    for (long long i = gtid; i < (long long)BATCH * LIN; i += nthr) {
        const int b = (int)(i / LIN);
        const int w0 = p32[i * 2 + 0];
        const int w1 = p32[i * 2 + 1];
        if (w1 > 0) is32_local = 1;
        // x candidate under both interpretations:
        // int32: x = w0 (pair i).  int64: pair i covers words 4i..4i+3; our i*2
        // indexing walks int32 PAIRS, so for int64 each position spans two pairs.
        // Handle int64 path in kernel B instead; here only compute int32-view max
        // plus int64-view max (even pair = {xlo,xhi}).
        int x32 = w0;                       // int32 interpretation
        if (x32 < 0) x32 = 0;
        atomicMax(&g_maxx[b], x32);         // harmless overcount guard below
        (void)x32;
        if (is32_local) {}
    }
    if (is32_local) atomicOr(&g_is32, 1);
}

// NOTE on g_maxx: for the int64 case the value computed above is wrong (mixes
// lo/hi words). Kernel B recomputes max properly for int64. To keep it simple
// and correct for both, kernel B does its OWN max pass (cheap: positions are
// ~1MB) and ignores g_maxx. g_maxx retained only to keep prep deterministic.

// ---------------------------------------------------------------------------
// Kernel B: per-batch max_x (dtype-aware) + scatter. One block per batch slice.
// grid = BATCH blocks x 512 threads (block-local max then scatter).
// ---------------------------------------------------------------------------
__global__ void scatter_kernel(const int* __restrict__ p32,
                               const unsigned char* __restrict__ pad) {
    const int b   = blockIdx.x;
    const int tid = threadIdx.x;
    const int nt  = blockDim.x;
    __shared__ int smax;
    if (tid == 0) smax = 0;
    __syncthreads();

    const int is32 = g_is32;

    // pass 1: max clamped x
    int lmax = 0;
    for (int l = tid; l < LIN; l += nt) {
        int xi;
        if (is32) {
            xi = p32[((long long)b * LIN + l) * 2];
        } else {
            const long long w = ((long long)b * LIN + l) * 4;
            int lo = p32[w + 0], hi = p32[w + 1];
            xi = (hi < 0) ? 0 : lo;
        }
        if (xi < 0) xi = 0;
        lmax = max(lmax, xi);
    }
    atomicMax(&smax, lmax);
    __syncthreads();
    const int wseg = (smax + 1) / KPOOL;

    // pass 2: scatter
    for (int l = tid; l < LIN; l += nt) {
        int xi, yi;
        if (is32) {
            xi = p32[((long long)b * LIN + l) * 2 + 0];
            yi = p32[((long long)b * LIN + l) * 2 + 1];
        } else {
            const long long w = ((long long)b * LIN + l) * 4;
            int xlo = p32[w + 0], xhi = p32[w + 1];
            int ylo = p32[w + 2], yhi = p32[w + 3];
            xi = (xhi < 0) ? -1 : xlo;
            yi = (yhi < 0) ? -1 : ylo;
        }
        if (xi < 0) xi = 0;
        if (yi < 0) yi = 0;
        int seg = xi / KPOOL + wseg * (yi / KPOOL);
        if (seg < 0) seg = 0;
        if (seg >= OUTLEN) seg = OUTLEN - 1;   // never corrupt scratch
        const int bs = b * OUTLEN + seg;

        atomicAdd(&g_cnt[bs], 1);              // mask = (any row maps here)

        if (!pad[(long long)b * LIN + l]) {    // only non-padded rows contribute
            int slot = atomicAdd(&g_vcnt[bs], 1);
            if (slot < SLOTS)
                ((int*)&g_idx4[bs])[slot] = b * LIN + l;  // absolute row id
        }
    }
}

// ---------------------------------------------------------------------------
// Kernel C: gather + mean + scale. One block per (batch, segment), 288 threads,
// each thread owns one float4 column. Single LDG.128 of the packed index, then
// 4 independent predicated streaming loads.
// ---------------------------------------------------------------------------
__global__ void __launch_bounds__(H4) pool_kernel(
    const float4* __restrict__ in,
    float4* __restrict__ out,
    float* __restrict__ mask_out)
{
    const int bs  = blockIdx.x;          // b * OUTLEN + seg
    const int tid = threadIdx.x;

    const int4 idx = g_idx4[bs];         // one LDG.128, uniform across block

    float4 acc = make_float4(0.f, 0.f, 0.f, 0.f);
    float4 v0, v1, v2, v3;
    const bool p0 = idx.x >= 0, p1 = idx.y >= 0, p2 = idx.z >= 0, p3 = idx.w >= 0;
    if (p0) v0 = __ldcs(&in[(long long)idx.x * H4 + tid]);
    if (p1) v1 = __ldcs(&in[(long long)idx.y * H4 + tid]);
    if (p2) v2 = __ldcs(&in[(long long)idx.z * H4 + tid]);
    if (p3) v3 = __ldcs(&in[(long long)idx.w * H4 + tid]);
    if (p0) { acc.x += v0.x; acc.y += v0.y; acc.z += v0.z; acc.w += v0.w; }
    if (p1) { acc.x += v1.x; acc.y += v1.y; acc.z += v1.z; acc.w += v1.w; }
    if (p2) { acc.x += v2.x; acc.y += v2.y; acc.z += v2.z; acc.w += v2.w; }
    if (p3) { acc.x += v3.x; acc.y += v3.y; acc.z += v3.z; acc.w += v3.w; }

    // pooled = sum / k^2, then * sqrt(H) :  sqrt(1152)/4
    const float SCALE = 8.4852813742385702928f;
    acc.x *= SCALE; acc.y *= SCALE; acc.z *= SCALE; acc.w *= SCALE;

    __stcs(&out[(long long)bs * H4 + tid], acc);

    if (mask_out != nullptr && tid == 0)
        mask_out[bs] = (g_cnt[bs] > 0) ? 1.0f : 0.0f;
}

// ---------------------------------------------------------------------------
extern "C" void kernel_launch(void* const* d_in, const int* in_sizes, int n_in,
                              void* d_out, int out_size)
{
    const float*         hs  = (const float*)d_in[0];          // [B, L, H] f32
    const int*           pos = (const int*)d_in[1];            // [B, L, 2] i32 or i64
    const unsigned char* pad = (const unsigned char*)d_in[2];  // [B, L] bool

    float* out = (float*)d_out;

    const long long hs_elems = (long long)BATCH * OUTLEN * HID;
    float* mask_out = nullptr;
    if ((long long)out_size >= hs_elems + (long long)BATCH * OUTLEN)
        mask_out = out + hs_elems;

    prep_kernel<<<64, 256>>>(pos);
    scatter_kernel<<<BATCH, 512>>>(pos, pad);
    pool_kernel<<<NSEG, H4>>>((const float4*)hs, (float4*)out, mask_out);
}

// round 5
// speedup vs baseline: 1.6139x; 1.6139x over previous
#include <cuda_runtime.h>
#include <cuda_bf16.h>

// Gemma4VisionPooler: 2x2 segment-mean pool (B=16, L=4096 -> 1024, H=1152) * sqrt(H)
// R4: R3's packed-int4 gather pool kernel (measured ~56us, at HBM roofline)
// + fixed preamble: no hot-address atomics in prep (R3's g_maxx atomicMax onto
// 16 addresses cost 46us of serialized L2-atomic time).

#define BATCH  16
#define LIN    4096
#define HID    1152
#define OUTLEN 1024
#define KPOOL  2          // sqrt(LIN/OUTLEN)
#define SLOTS  4          // k^2 rows per segment
#define H4     (HID / 4)  // 288 float4 per row
#define NSEG   (BATCH * OUTLEN)

// Scratch (allocation-free rule: __device__ globals)
__device__ int  g_cnt[NSEG];    // total rows per segment (incl. padded) -> mask
__device__ int  g_vcnt[NSEG];   // valid (non-padded) slot cursor
__device__ int4 g_idx4[NSEG];   // packed absolute row ids, -1 = empty
__device__ int  g_is32;         // 1 if positions are int32

// ---------------------------------------------------------------------------
// Kernel A: reset scratch + dtype detect. grid = 64 x 256.
// Detection: view positions as int32 words. int64 layout has odd words = high
// words (0 or -1); int32 layout has odd words = y coords, which exceed 0.
// Block-local reduction -> at most one global atomic per block.
// ---------------------------------------------------------------------------
__global__ void prep_kernel(const int* __restrict__ p32) {
    const int gtid = blockIdx.x * blockDim.x + threadIdx.x;
    const int nthr = gridDim.x * blockDim.x;

    if (gtid == 0) g_is32 = 0;   // separate-launch ordering covers visibility

    for (int i = gtid; i < NSEG; i += nthr) {
        g_cnt[i]  = 0;
        g_vcnt[i] = 0;
        g_idx4[i] = make_int4(-1, -1, -1, -1);
    }

    int found = 0;
    const long long nwords = (long long)BATCH * LIN * 2;
    for (long long i = gtid * 2 + 1; i < nwords; i += (long long)nthr * 2)
        if (p32[i] > 0) found = 1;

    // warp + block reduce, single atomic per block (and only if set)
    found = __syncthreads_or(found);
    if (found && threadIdx.x == 0) atomicOr(&g_is32, 1);
}

// ---------------------------------------------------------------------------
// Kernel B: per-batch max_x (dtype-aware) + scatter. One block per batch.
// Atomics here hit 16K distinct addresses -- no contention problem.
// ---------------------------------------------------------------------------
__global__ void scatter_kernel(const int* __restrict__ p32,
                               const unsigned char* __restrict__ pad) {
    const int b   = blockIdx.x;
    const int tid = threadIdx.x;
    const int nt  = blockDim.x;
    __shared__ int smax;
    if (tid == 0) smax = 0;
    __syncthreads();

    const int is32 = g_is32;

    // pass 1: max clamped x (shared-mem atomic: cheap)
    int lmax = 0;
    for (int l = tid; l < LIN; l += nt) {
        int xi;
        if (is32) {
            xi = p32[((long long)b * LIN + l) * 2];
        } else {
            const long long w = ((long long)b * LIN + l) * 4;
            int lo = p32[w + 0], hi = p32[w + 1];
            xi = (hi < 0) ? 0 : lo;
        }
        if (xi < 0) xi = 0;
        lmax = max(lmax, xi);
    }
    atomicMax(&smax, lmax);
    __syncthreads();
    const int wseg = (smax + 1) / KPOOL;

    // pass 2: scatter row ids into segment slot lists
    for (int l = tid; l < LIN; l += nt) {
        int xi, yi;
        if (is32) {
            xi = p32[((long long)b * LIN + l) * 2 + 0];
            yi = p32[((long long)b * LIN + l) * 2 + 1];
        } else {
            const long long w = ((long long)b * LIN + l) * 4;
            int xlo = p32[w + 0], xhi = p32[w + 1];
            int ylo = p32[w + 2], yhi = p32[w + 3];
            xi = (xhi < 0) ? -1 : xlo;
            yi = (yhi < 0) ? -1 : ylo;
        }
        if (xi < 0) xi = 0;
        if (yi < 0) yi = 0;
        int seg = xi / KPOOL + wseg * (yi / KPOOL);
        if (seg < 0) seg = 0;
        if (seg >= OUTLEN) seg = OUTLEN - 1;   // never corrupt scratch
        const int bs = b * OUTLEN + seg;

        atomicAdd(&g_cnt[bs], 1);              // mask = (any row maps here)

        if (!pad[(long long)b * LIN + l]) {    // only non-padded rows contribute
            int slot = atomicAdd(&g_vcnt[bs], 1);
            if (slot < SLOTS)
                ((int*)&g_idx4[bs])[slot] = b * LIN + l;  // absolute row id
        }
    }
}

// ---------------------------------------------------------------------------
// Kernel C: gather + mean + scale. One block per (batch, segment), 288 threads,
// each thread owns one float4 column. Single LDG.128 of the packed index, then
// 4 independent predicated streaming loads. Measured ~at HBM roofline.
// ---------------------------------------------------------------------------
__global__ void __launch_bounds__(H4) pool_kernel(
    const float4* __restrict__ in,
    float4* __restrict__ out,
    float* __restrict__ mask_out)
{
    const int bs  = blockIdx.x;          // b * OUTLEN + seg
    const int tid = threadIdx.x;

    const int4 idx = g_idx4[bs];         // one LDG.128, uniform across block

    float4 acc = make_float4(0.f, 0.f, 0.f, 0.f);
    float4 v0, v1, v2, v3;
    const bool p0 = idx.x >= 0, p1 = idx.y >= 0, p2 = idx.z >= 0, p3 = idx.w >= 0;
    if (p0) v0 = __ldcs(&in[(long long)idx.x * H4 + tid]);
    if (p1) v1 = __ldcs(&in[(long long)idx.y * H4 + tid]);
    if (p2) v2 = __ldcs(&in[(long long)idx.z * H4 + tid]);
    if (p3) v3 = __ldcs(&in[(long long)idx.w * H4 + tid]);
    if (p0) { acc.x += v0.x; acc.y += v0.y; acc.z += v0.z; acc.w += v0.w; }
    if (p1) { acc.x += v1.x; acc.y += v1.y; acc.z += v1.z; acc.w += v1.w; }
    if (p2) { acc.x += v2.x; acc.y += v2.y; acc.z += v2.z; acc.w += v2.w; }
    if (p3) { acc.x += v3.x; acc.y += v3.y; acc.z += v3.z; acc.w += v3.w; }

    // pooled = sum / k^2, then * sqrt(H) :  sqrt(1152)/4
    const float SCALE = 8.4852813742385702928f;
    acc.x *= SCALE; acc.y *= SCALE; acc.z *= SCALE; acc.w *= SCALE;

    __stcs(&out[(long long)bs * H4 + tid], acc);

    if (mask_out != nullptr && tid == 0)
        mask_out[bs] = (g_cnt[bs] > 0) ? 1.0f : 0.0f;
}

// ---------------------------------------------------------------------------
extern "C" void kernel_launch(void* const* d_in, const int* in_sizes, int n_in,
                              void* d_out, int out_size)
{
    const float*         hs  = (const float*)d_in[0];          // [B, L, H] f32
    const int*           pos = (const int*)d_in[1];            // [B, L, 2] i32 or i64
    const unsigned char* pad = (const unsigned char*)d_in[2];  // [B, L] bool

    float* out = (float*)d_out;

    const long long hs_elems = (long long)BATCH * OUTLEN * HID;
    float* mask_out = nullptr;
    if ((long long)out_size >= hs_elems + (long long)BATCH * OUTLEN)
        mask_out = out + hs_elems;

    prep_kernel<<<64, 256>>>(pos);
    scatter_kernel<<<BATCH, 512>>>(pos, pad);
    pool_kernel<<<NSEG, H4>>>((const float4*)hs, (float4*)out, mask_out);
}

// round 6
// speedup vs baseline: 1.6762x; 1.0386x over previous
#include <cuda_runtime.h>
#include <cuda_bf16.h>

// Gemma4VisionPooler: 2x2 segment-mean pool (B=16, L=4096 -> 1024, H=1152) * sqrt(H)
// R5: two kernels only.
//   scatter_kernel: one block per batch — resets its own scratch region,
//     detects position dtype, computes max_x, builds packed int4 gather lists.
//     (Per-batch scratch ownership makes the R4 prep kernel's cross-launch
//     ordering unnecessary; __syncthreads covers it.)
//   pool_kernel: measured at HBM roofline (~56us for 378MB).

#define BATCH  16
#define LIN    4096
#define HID    1152
#define OUTLEN 1024
#define KPOOL  2          // sqrt(LIN/OUTLEN)
#define SLOTS  4          // k^2 rows per segment
#define H4     (HID / 4)  // 288 float4 per row
#define NSEG   (BATCH * OUTLEN)
#define STHREADS 1024

// Scratch (allocation-free rule: __device__ globals)
__device__ int  g_cnt[NSEG];    // total rows per segment (incl. padded) -> mask
__device__ int  g_vcnt[NSEG];   // valid (non-padded) slot cursor
__device__ int4 g_idx4[NSEG];   // packed absolute row ids, -1 = empty

// ---------------------------------------------------------------------------
// Fused index build. One block per batch, 1024 threads.
// ---------------------------------------------------------------------------
__global__ void __launch_bounds__(STHREADS) scatter_kernel(
    const int* __restrict__ p32,
    const unsigned char* __restrict__ pad)
{
    const int b   = blockIdx.x;
    const int tid = threadIdx.x;

    __shared__ int sx[LIN];
    __shared__ int sy[LIN];
    __shared__ int smax;
    __shared__ int s_is32;
    if (tid == 0) { smax = 0; s_is32 = 0; }

    // reset this batch's scratch region (exclusively owned by this block)
    for (int s = tid; s < OUTLEN; s += STHREADS) {
        const int bs = b * OUTLEN + s;
        g_cnt[bs]  = 0;
        g_vcnt[bs] = 0;
        g_idx4[bs] = make_int4(-1, -1, -1, -1);
    }
    __syncthreads();

    // dtype detect over this batch's words (int32 view): int64 layout has odd
    // words = high words (0/-1); int32 layout has odd words = y, which exceed 0.
    {
        int found = 0;
        const int* base = p32 + (long long)b * LIN * 2;
        for (int i = tid * 2 + 1; i < LIN * 2; i += STHREADS * 2)
            if (base[i] > 0) found = 1;
        if (__syncthreads_or(found) == 0) { /* int64 */ }
        else if (tid == 0) s_is32 = 1;
    }
    __syncthreads();
    const int is32 = s_is32;

    // decode positions once into shared, accumulate max clamped x
    int lmax = 0;
    for (int l = tid; l < LIN; l += STHREADS) {
        int xi, yi;
        if (is32) {
            xi = p32[((long long)b * LIN + l) * 2 + 0];
            yi = p32[((long long)b * LIN + l) * 2 + 1];
        } else {
            const long long w = ((long long)b * LIN + l) * 4;
            int xlo = p32[w + 0], xhi = p32[w + 1];
            int ylo = p32[w + 2], yhi = p32[w + 3];
            xi = (xhi < 0) ? -1 : xlo;
            yi = (yhi < 0) ? -1 : ylo;
        }
        if (xi < 0) xi = 0;
        if (yi < 0) yi = 0;
        sx[l] = xi;
        sy[l] = yi;
        lmax = max(lmax, xi);
    }
    atomicMax(&smax, lmax);   // shared-mem atomic: cheap
    __syncthreads();
    const int wseg = (smax + 1) / KPOOL;

    // scatter row ids into segment slot lists (16K distinct atomic addresses)
    for (int l = tid; l < LIN; l += STHREADS) {
        int seg = sx[l] / KPOOL + wseg * (sy[l] / KPOOL);
        if (seg < 0) seg = 0;
        if (seg >= OUTLEN) seg = OUTLEN - 1;   // never corrupt scratch
        const int bs = b * OUTLEN + seg;

        atomicAdd(&g_cnt[bs], 1);              // mask = (any row maps here)

        if (!pad[(long long)b * LIN + l]) {    // only non-padded rows contribute
            int slot = atomicAdd(&g_vcnt[bs], 1);
            if (slot < SLOTS)
                ((int*)&g_idx4[bs])[slot] = b * LIN + l;  // absolute row id
        }
    }
}

// ---------------------------------------------------------------------------
// Gather + mean + scale. One block per (batch, segment), 288 threads, each
// thread owns one float4 column. Single LDG.128 of the packed index, then 4
// independent predicated streaming loads. At HBM roofline.
// ---------------------------------------------------------------------------
__global__ void __launch_bounds__(H4) pool_kernel(
    const float4* __restrict__ in,
    float4* __restrict__ out,
    float* __restrict__ mask_out)
{
    const int bs  = blockIdx.x;          // b * OUTLEN + seg
    const int tid = threadIdx.x;

    const int4 idx = g_idx4[bs];         // one LDG.128, uniform across block

    float4 acc = make_float4(0.f, 0.f, 0.f, 0.f);
    float4 v0, v1, v2, v3;
    const bool p0 = idx.x >= 0, p1 = idx.y >= 0, p2 = idx.z >= 0, p3 = idx.w >= 0;
    if (p0) v0 = __ldcs(&in[(long long)idx.x * H4 + tid]);
    if (p1) v1 = __ldcs(&in[(long long)idx.y * H4 + tid]);
    if (p2) v2 = __ldcs(&in[(long long)idx.z * H4 + tid]);
    if (p3) v3 = __ldcs(&in[(long long)idx.w * H4 + tid]);
    if (p0) { acc.x += v0.x; acc.y += v0.y; acc.z += v0.z; acc.w += v0.w; }
    if (p1) { acc.x += v1.x; acc.y += v1.y; acc.z += v1.z; acc.w += v1.w; }
    if (p2) { acc.x += v2.x; acc.y += v2.y; acc.z += v2.z; acc.w += v2.w; }
    if (p3) { acc.x += v3.x; acc.y += v3.y; acc.z += v3.z; acc.w += v3.w; }

    // pooled = sum / k^2, then * sqrt(H) :  sqrt(1152)/4
    const float SCALE = 8.4852813742385702928f;
    acc.x *= SCALE; acc.y *= SCALE; acc.z *= SCALE; acc.w *= SCALE;

    __stcs(&out[(long long)bs * H4 + tid], acc);

    if (mask_out != nullptr && tid == 0)
        mask_out[bs] = (g_cnt[bs] > 0) ? 1.0f : 0.0f;
}

// ---------------------------------------------------------------------------
extern "C" void kernel_launch(void* const* d_in, const int* in_sizes, int n_in,
                              void* d_out, int out_size)
{
    const float*         hs  = (const float*)d_in[0];          // [B, L, H] f32
    const int*           pos = (const int*)d_in[1];            // [B, L, 2] i32 or i64
    const unsigned char* pad = (const unsigned char*)d_in[2];  // [B, L] bool

    float* out = (float*)d_out;

    const long long hs_elems = (long long)BATCH * OUTLEN * HID;
    float* mask_out = nullptr;
    if ((long long)out_size >= hs_elems + (long long)BATCH * OUTLEN)
        mask_out = out + hs_elems;

    scatter_kernel<<<BATCH, STHREADS>>>(pos, pad);
    pool_kernel<<<NSEG, H4>>>((const float4*)hs, (float4*)out, mask_out);
}